// round 15
// baseline (speedup 1.0000x reference)
#include <cuda_runtime.h>
#include <math_constants.h>

#define NROWS 4096
#define M_REC 4000
#define M_SUB 20000
#define MAXG  10

// Scratch (allocation-free per harness rules)
__device__ int  g_ri[NROWS];
__device__ int  g_si[NROWS];
__device__ int2 g_tab[NROWS];   // {si, p_self} per j

// ---------------------------------------------------------------------------
// Row argmax: one block per row, float4 vectorized, 4-deep load batch.
// Per-vector lane computed inline (3 independent cmp/sel off the critical
// chain) so NO post-scan reload is needed -> DRAM traffic is exactly the
// compulsory 393 MB. Tie-break matches jnp.argmax (first index): m is
// bit-identical to one component; first-equality x->w = smallest lane;
// strict '>' + ascending visit order = first vector.
// ---------------------------------------------------------------------------
template <int M>
__device__ __forceinline__ void row_argmax(const float* __restrict__ mat,
                                           int row, int* __restrict__ out_idx)
{
    const float4* __restrict__ rp =
        reinterpret_cast<const float4*>(mat + (size_t)row * M);
    constexpr int M4 = M / 4;   // both 4000 and 20000 divisible by 4

    float best = -CUDART_INF_F;
    int   bidx = 0;

    // lane within vector: first equality = smallest index (independent ops)
    #define LANE(vv, mm) \
        ((vv).x == (mm) ? 0 : ((vv).y == (mm) ? 1 : ((vv).z == (mm) ? 2 : 3)))

    int i = threadIdx.x;
    for (; i + 3 * 256 < M4; i += 4 * 256) {
        float4 v0 = rp[i];
        float4 v1 = rp[i + 256];
        float4 v2 = rp[i + 512];
        float4 v3 = rp[i + 768];
        float m0 = fmaxf(fmaxf(v0.x, v0.y), fmaxf(v0.z, v0.w));
        float m1 = fmaxf(fmaxf(v1.x, v1.y), fmaxf(v1.z, v1.w));
        float m2 = fmaxf(fmaxf(v2.x, v2.y), fmaxf(v2.z, v2.w));
        float m3 = fmaxf(fmaxf(v3.x, v3.y), fmaxf(v3.z, v3.w));
        int l0 = LANE(v0, m0);
        int l1 = LANE(v1, m1);
        int l2 = LANE(v2, m2);
        int l3 = LANE(v3, m3);
        if (m0 > best) { best = m0; bidx = 4 * i          + l0; }
        if (m1 > best) { best = m1; bidx = 4 * (i + 256)  + l1; }
        if (m2 > best) { best = m2; bidx = 4 * (i + 512)  + l2; }
        if (m3 > best) { best = m3; bidx = 4 * (i + 768)  + l3; }
    }
    for (; i < M4; i += 256) {
        float4 v = rp[i];
        float m = fmaxf(fmaxf(v.x, v.y), fmaxf(v.z, v.w));
        int   l = LANE(v, m);
        if (m > best) { best = m; bidx = 4 * i + l; }
    }
    #undef LANE

    // Warp reduce (tie-break: smaller index wins on equal value)
    #pragma unroll
    for (int off = 16; off > 0; off >>= 1) {
        float ov = __shfl_down_sync(0xFFFFFFFFu, best, off);
        int   oi = __shfl_down_sync(0xFFFFFFFFu, bidx, off);
        if (ov > best || (ov == best && oi < bidx)) { best = ov; bidx = oi; }
    }

    // Block reduce across 8 warps
    __shared__ float s_val[8];
    __shared__ int   s_idx[8];
    const int wid = threadIdx.x >> 5;
    const int lid = threadIdx.x & 31;
    if (lid == 0) { s_val[wid] = best; s_idx[wid] = bidx; }
    __syncthreads();
    if (wid == 0) {
        best = (lid < 8) ? s_val[lid] : -CUDART_INF_F;
        bidx = (lid < 8) ? s_idx[lid] : 0x7FFFFFFF;
        #pragma unroll
        for (int off = 4; off > 0; off >>= 1) {
            float ov = __shfl_down_sync(0xFFFFFFFFu, best, off);
            int   oi = __shfl_down_sync(0xFFFFFFFFu, bidx, off);
            if (ov > best || (ov == best && oi < bidx)) { best = ov; bidx = oi; }
        }
        if (lid == 0) out_idx[row] = bidx;
    }
}

// Merged launch: blocks [0, NROWS) do the big Substitute rows (scheduled
// first to minimize the tail), blocks [NROWS, 2*NROWS) do Recommended rows.
__global__ void __launch_bounds__(256) argmax_both_kernel(
    const float* __restrict__ rec, const float* __restrict__ sub,
    int* __restrict__ ri, int* __restrict__ si)
{
    if (blockIdx.x < NROWS)
        row_argmax<M_SUB>(sub, blockIdx.x, si);
    else
        row_argmax<M_REC>(rec, blockIdx.x - NROWS, ri);
}

// ---------------------------------------------------------------------------
// Prep: ALL scattered/latency work, once, with 4096-way parallelism.
// One thread per j: builds g_tab[j] = {si[j], p_self[j]}, writes Tprefer
// (out[0:N]) and Thaptic (out[2N:3N]). Three dependent load rounds, each
// round fully parallel chip-wide.
// NOTE: Vid is int32 on-device (JAX default config downcasts jnp.int64).
// ---------------------------------------------------------------------------
__global__ void __launch_bounds__(128) prep_kernel(
    const float* __restrict__ preference,
    const float* __restrict__ structure,
    const int*   __restrict__ Vid,
    float* __restrict__ out)
{
    const int j = blockIdx.x * 128 + threadIdx.x;
    // round 1 (independent)
    const int s = g_si[j];
    const int r = g_ri[j];
    // round 2 (independent of each other)
    const float p = __ldg(&preference[(size_t)s * NROWS + j]);
    const int   v = Vid[MAXG + r];          // vid_s[ri[j]], 0 <= v < P
    // round 3 (independent of each other)
    const float po = __ldg(&preference[(size_t)v * NROWS + j]);
    const float th = __ldg(&structure[(size_t)s * M_REC + r]);

    g_tab[j] = make_int2(s, __float_as_int(p));
    out[j] = p - po;                        // Tprefer
    out[2 * NROWS + j] = th;                // Thaptic
}

// ---------------------------------------------------------------------------
// Tsocial (out[N:2N]): 128 blocks x 512 threads, 32 i per block, 16 subs
// per i. Table loaded coalesced from g_tab (32 KB unique -> L2-hot after
// the first wave). Scan: addr = k*16+sub -> a warp's 16 sub-lanes read 16
// consecutive int2 (128 B, exactly 32 banks, conflict-free) with 2x
// broadcast across its 2 i-groups. 16 warps/SM hide LDS latency.
// Fixed shfl tree -> deterministic.
// ---------------------------------------------------------------------------
__global__ void __launch_bounds__(512) tsocial_kernel(float* __restrict__ out)
{
    __shared__ int2 sj[NROWS];   // 32 KB

    // Coalesced table load: 8 slots per thread, all independent.
    #pragma unroll
    for (int k = 0; k < NROWS / 512; k++)
        sj[threadIdx.x + k * 512] = g_tab[threadIdx.x + k * 512];
    __syncthreads();

    const int i_local = threadIdx.x >> 4;       // 0..31
    const int sub     = threadIdx.x & 15;       // 0..15
    const int i       = blockIdx.x * 32 + i_local;

    const int   si_i = sj[i].x;
    const float p_i  = __int_as_float(sj[i].y);

    float acc = 0.0f;
    #pragma unroll 16
    for (int k = 0; k < NROWS / 16; k++) {
        const int2 v = sj[k * 16 + sub];
        if (v.x == si_i) acc += fminf(p_i, __int_as_float(v.y));
    }

    // Reduce the 16 sub-lanes of this i (consecutive lanes in the warp).
    #pragma unroll
    for (int off = 8; off > 0; off >>= 1)
        acc += __shfl_down_sync(0xFFFFFFFFu, acc, off);

    // Scan included j == i (si_i == si_i always); fminf(p_i, p_i) == p_i.
    if (sub == 0) out[NROWS + i] = acc - p_i;
}

// ---------------------------------------------------------------------------
extern "C" void kernel_launch(void* const* d_in, const int* in_sizes, int n_in,
                              void* d_out, int out_size)
{
    const float* Recommended_m = (const float*)d_in[0];
    const float* Substitute_m  = (const float*)d_in[1];
    // d_in[2] ItemGroups_m : unused
    const int*   Vid           = (const int*)d_in[3];
    // d_in[4..7] VUU/KUU/Vscore/Kscore : unused
    const float* preference    = (const float*)d_in[8];
    const float* structure     = (const float*)d_in[9];
    float* out = (float*)d_out;

    int* d_ri; int* d_si;
    cudaGetSymbolAddress((void**)&d_ri, g_ri);
    cudaGetSymbolAddress((void**)&d_si, g_si);

    argmax_both_kernel<<<2 * NROWS, 256>>>(Recommended_m, Substitute_m, d_ri, d_si);
    prep_kernel<<<NROWS / 128, 128>>>(preference, structure, Vid, out);
    tsocial_kernel<<<NROWS / 32, 512>>>(out);
}

// round 17
// speedup vs baseline: 1.0698x; 1.0698x over previous
#include <cuda_runtime.h>
#include <math_constants.h>

#define NROWS 4096
#define M_REC 4000
#define M_SUB 20000
#define MAXG  10

// Scratch (allocation-free per harness rules)
__device__ int  g_ri[NROWS];
__device__ int  g_si[NROWS];
__device__ int2 g_tab[NROWS];   // {si, p_self} per j

// ---------------------------------------------------------------------------
// Row argmax: one block per row, float4 vectorized, 4-deep load batch.
// (Exact best-measured R12 config: 67.3us @ 75.7% DRAM. The inline-lane
// variant regressed — issue slots are the secondary resource here; the
// post-scan reload is L2-hot and costs ~3% extra traffic only.)
// Tie-break matches jnp.argmax (first index).
// ---------------------------------------------------------------------------
template <int M>
__device__ __forceinline__ void row_argmax(const float* __restrict__ mat,
                                           int row, int* __restrict__ out_idx)
{
    const float4* __restrict__ rp =
        reinterpret_cast<const float4*>(mat + (size_t)row * M);
    constexpr int M4 = M / 4;   // both 4000 and 20000 divisible by 4

    float best = -CUDART_INF_F;
    int   bvec = (threadIdx.x < M4) ? (int)threadIdx.x : 0;

    int i = threadIdx.x;
    for (; i + 3 * 256 < M4; i += 4 * 256) {
        float4 v0 = rp[i];
        float4 v1 = rp[i + 256];
        float4 v2 = rp[i + 512];
        float4 v3 = rp[i + 768];
        float m0 = fmaxf(fmaxf(v0.x, v0.y), fmaxf(v0.z, v0.w));
        float m1 = fmaxf(fmaxf(v1.x, v1.y), fmaxf(v1.z, v1.w));
        float m2 = fmaxf(fmaxf(v2.x, v2.y), fmaxf(v2.z, v2.w));
        float m3 = fmaxf(fmaxf(v3.x, v3.y), fmaxf(v3.z, v3.w));
        // strict '>' keeps the earliest vector on ties (ascending visit order)
        if (m0 > best) { best = m0; bvec = i;       }
        if (m1 > best) { best = m1; bvec = i + 256; }
        if (m2 > best) { best = m2; bvec = i + 512; }
        if (m3 > best) { best = m3; bvec = i + 768; }
    }
    for (; i < M4; i += 256) {
        float4 v = rp[i];
        float m = fmaxf(fmaxf(v.x, v.y), fmaxf(v.z, v.w));
        if (m > best) { best = m; bvec = i; }
    }

    // Recover lane within winning vector (first equality = smallest index).
    // best is bit-identical to one of the 4 elements, so '==' is exact.
    // This row just streamed through this SM -> reload is L1/L2-hot.
    {
        float4 v = rp[bvec];
        int b = bvec * 4;
        int bidx = b + 3;
        if (v.z == best) bidx = b + 2;
        if (v.y == best) bidx = b + 1;
        if (v.x == best) bidx = b;
        bvec = bidx;
    }
    int bidx = bvec;

    // Warp reduce (tie-break: smaller index wins on equal value)
    #pragma unroll
    for (int off = 16; off > 0; off >>= 1) {
        float ov = __shfl_down_sync(0xFFFFFFFFu, best, off);
        int   oi = __shfl_down_sync(0xFFFFFFFFu, bidx, off);
        if (ov > best || (ov == best && oi < bidx)) { best = ov; bidx = oi; }
    }

    // Block reduce across 8 warps
    __shared__ float s_val[8];
    __shared__ int   s_idx[8];
    const int wid = threadIdx.x >> 5;
    const int lid = threadIdx.x & 31;
    if (lid == 0) { s_val[wid] = best; s_idx[wid] = bidx; }
    __syncthreads();
    if (wid == 0) {
        best = (lid < 8) ? s_val[lid] : -CUDART_INF_F;
        bidx = (lid < 8) ? s_idx[lid] : 0x7FFFFFFF;
        #pragma unroll
        for (int off = 4; off > 0; off >>= 1) {
            float ov = __shfl_down_sync(0xFFFFFFFFu, best, off);
            int   oi = __shfl_down_sync(0xFFFFFFFFu, bidx, off);
            if (ov > best || (ov == best && oi < bidx)) { best = ov; bidx = oi; }
        }
        if (lid == 0) out_idx[row] = bidx;
    }
}

// Merged launch: blocks [0, NROWS) do the big Substitute rows (scheduled
// first to minimize the tail), blocks [NROWS, 2*NROWS) do Recommended rows.
__global__ void __launch_bounds__(256) argmax_both_kernel(
    const float* __restrict__ rec, const float* __restrict__ sub,
    int* __restrict__ ri, int* __restrict__ si)
{
    if (blockIdx.x < NROWS)
        row_argmax<M_SUB>(sub, blockIdx.x, si);
    else
        row_argmax<M_REC>(rec, blockIdx.x - NROWS, ri);
}

// ---------------------------------------------------------------------------
// Prep: ALL scattered/latency work, once, with 4096-way parallelism.
// One thread per j: builds g_tab[j] = {si[j], p_self[j]}, writes Tprefer
// (out[0:N]) and Thaptic (out[2N:3N]). Three dependent load rounds, each
// round fully parallel chip-wide. 128 blocks x 32 threads: one warp per SM
// so each SM's L1tex queue serves only ONE scattered round (32 wavefronts)
// at a time instead of four queued warps.
// NOTE: Vid is int32 on-device (JAX default config downcasts jnp.int64).
// ---------------------------------------------------------------------------
__global__ void __launch_bounds__(32) prep_kernel(
    const float* __restrict__ preference,
    const float* __restrict__ structure,
    const int*   __restrict__ Vid,
    float* __restrict__ out)
{
    const int j = blockIdx.x * 32 + threadIdx.x;
    // round 1 (independent)
    const int s = g_si[j];
    const int r = g_ri[j];
    // round 2 (independent of each other)
    const float p = __ldg(&preference[(size_t)s * NROWS + j]);
    const int   v = Vid[MAXG + r];          // vid_s[ri[j]], 0 <= v < P
    // round 3 (independent of each other)
    const float po = __ldg(&preference[(size_t)v * NROWS + j]);
    const float th = __ldg(&structure[(size_t)s * M_REC + r]);

    g_tab[j] = make_int2(s, __float_as_int(p));
    out[j] = p - po;                        // Tprefer
    out[2 * NROWS + j] = th;                // Thaptic
}

// ---------------------------------------------------------------------------
// Tsocial (out[N:2N]): 128 blocks x 512 threads, 32 i per block, 16 subs
// per i. Table loaded coalesced from g_tab (32 KB unique -> L2-hot after
// the first wave). Scan: addr = k*16+sub -> a warp's 16 sub-lanes read 16
// consecutive int2 (128 B, exactly 32 banks, conflict-free) with 2x
// broadcast across its 2 i-groups. 16 warps/SM hide LDS latency.
// Fixed shfl tree -> deterministic.
// ---------------------------------------------------------------------------
__global__ void __launch_bounds__(512) tsocial_kernel(float* __restrict__ out)
{
    __shared__ int2 sj[NROWS];   // 32 KB

    // Coalesced table load: 8 slots per thread, all independent.
    #pragma unroll
    for (int k = 0; k < NROWS / 512; k++)
        sj[threadIdx.x + k * 512] = g_tab[threadIdx.x + k * 512];
    __syncthreads();

    const int i_local = threadIdx.x >> 4;       // 0..31
    const int sub     = threadIdx.x & 15;       // 0..15
    const int i       = blockIdx.x * 32 + i_local;

    const int   si_i = sj[i].x;
    const float p_i  = __int_as_float(sj[i].y);

    float acc = 0.0f;
    #pragma unroll 16
    for (int k = 0; k < NROWS / 16; k++) {
        const int2 v = sj[k * 16 + sub];
        if (v.x == si_i) acc += fminf(p_i, __int_as_float(v.y));
    }

    // Reduce the 16 sub-lanes of this i (consecutive lanes in the warp).
    #pragma unroll
    for (int off = 8; off > 0; off >>= 1)
        acc += __shfl_down_sync(0xFFFFFFFFu, acc, off);

    // Scan included j == i (si_i == si_i always); fminf(p_i, p_i) == p_i.
    if (sub == 0) out[NROWS + i] = acc - p_i;
}

// ---------------------------------------------------------------------------
extern "C" void kernel_launch(void* const* d_in, const int* in_sizes, int n_in,
                              void* d_out, int out_size)
{
    const float* Recommended_m = (const float*)d_in[0];
    const float* Substitute_m  = (const float*)d_in[1];
    // d_in[2] ItemGroups_m : unused
    const int*   Vid           = (const int*)d_in[3];
    // d_in[4..7] VUU/KUU/Vscore/Kscore : unused
    const float* preference    = (const float*)d_in[8];
    const float* structure     = (const float*)d_in[9];
    float* out = (float*)d_out;

    int* d_ri; int* d_si;
    cudaGetSymbolAddress((void**)&d_ri, g_ri);
    cudaGetSymbolAddress((void**)&d_si, g_si);

    argmax_both_kernel<<<2 * NROWS, 256>>>(Recommended_m, Substitute_m, d_ri, d_si);
    prep_kernel<<<NROWS / 32, 32>>>(preference, structure, Vid, out);
    tsocial_kernel<<<NROWS / 32, 512>>>(out);
}